// round 1
// baseline (speedup 1.0000x reference)
#include <cuda_runtime.h>
#include <stdint.h>

// YOLO loss, fully fused single-pass reduction.
// Inputs (metadata order): pred_tensor (N,28,28,30) f32, target_boxes (N,28,28,4) f32,
// target_cls (N,28,28,20) f32, has_object_map (N,28,28) bool (dtype auto-detected).
// Output: 5 floats [total, reg, contain, noobj, cls] / N.

#define SGRID 28
#define L_COORD 5.0
#define L_NOOBJ 0.5

__device__ double g_acc[4];     // [cls, noobj_raw, reg_raw(xy+wh), contain]
__device__ int    g_mask_mode;  // 0 = uint8/bool, 1 = int32, 2 = float32

// One block: classify mask dtype from byte patterns + zero accumulators.
// f32 1.0f has bytes {00,00,80,3F} -> bytes > 1 present.
// bool8 has 0/1 bytes at arbitrary offsets -> nonzero at i%4!=0.
// int32 0/1 has nonzero only at i%4==0 with value 1.
__global__ void detect_and_zero_kernel(const unsigned char* __restrict__ m) {
    __shared__ int s_gt1, s_off;
    if (threadIdx.x == 0) { s_gt1 = 0; s_off = 0; }
    __syncthreads();
    int lgt1 = 0, loff = 0;
    // scan 4096 bytes (safe: smallest possible mask buffer is 802816 bytes)
    for (int i = threadIdx.x * 16; i < 4096; i += blockDim.x * 16) {
        #pragma unroll
        for (int k = 0; k < 16; k++) {
            unsigned char b = m[i + k];
            if (b > 1) lgt1 = 1;
            if (((i + k) & 3) != 0 && b != 0) loff = 1;
        }
    }
    if (lgt1) atomicOr(&s_gt1, 1);
    if (loff) atomicOr(&s_off, 1);
    __syncthreads();
    if (threadIdx.x == 0) {
        g_mask_mode = s_gt1 ? 2 : (s_off ? 0 : 1);
        #pragma unroll
        for (int k = 0; k < 4; k++) g_acc[k] = 0.0;
    }
}

__device__ __forceinline__ float iou_vs_t(const float* b, float t0, float t1,
                                          float t2, float t3) {
    const float invS = 1.0f / (float)SGRID;
    float bx = b[0] * invS, by = b[1] * invS;
    float b0 = bx - 0.5f * b[2], b1 = by - 0.5f * b[3];
    float b2 = bx + 0.5f * b[2], b3 = by + 0.5f * b[3];
    float lt0 = fmaxf(b0, t0), lt1 = fmaxf(b1, t1);
    float rb0 = fminf(b2, t2), rb1 = fminf(b3, t3);
    float w = fmaxf(rb0 - lt0, 0.0f), h = fmaxf(rb1 - lt1, 0.0f);
    float inter = w * h;
    float a1 = (b2 - b0) * (b3 - b1);
    float a2 = (t2 - t0) * (t3 - t1);
    float denom = a1 + a2 - inter;
    return inter / (denom > 0.0f ? denom : 1.0f);
}

__global__ void __launch_bounds__(256)
yolo_loss_kernel(const float* __restrict__ pred,
                 const float* __restrict__ tbox,
                 const float* __restrict__ tcls,
                 const void*  __restrict__ mask,
                 int ncells) {
    int idx = blockIdx.x * blockDim.x + threadIdx.x;
    float s_cls = 0.0f, s_no = 0.0f, s_reg = 0.0f, s_ct = 0.0f;
    const int mode = g_mask_mode;

    if (idx < ncells) {
        float fm;
        if (mode == 0)      fm = ((const unsigned char*)mask)[idx] ? 1.0f : 0.0f;
        else if (mode == 1) fm = ((const int*)mask)[idx]           ? 1.0f : 0.0f;
        else                fm = (((const float*)mask)[idx] != 0.0f) ? 1.0f : 0.0f;

        // pred: 30 floats / cell, stride 120 B -> 8B-aligned: 15 x float2
        float p[30];
        const float2* p2 = (const float2*)(pred + (size_t)idx * 30);
        #pragma unroll
        for (int i = 0; i < 15; i++) {
            float2 v = __ldg(p2 + i);
            p[2 * i] = v.x; p[2 * i + 1] = v.y;
        }
        // target box: 16B-aligned float4
        float4 tb = __ldg((const float4*)tbox + idx);
        // target cls: 20 floats, stride 80 B -> 16B-aligned: 5 x float4
        float tc[20];
        const float4* c4 = (const float4*)(tcls + (size_t)idx * 20);
        #pragma unroll
        for (int i = 0; i < 5; i++) {
            float4 v = __ldg(c4 + i);
            tc[4 * i] = v.x; tc[4 * i + 1] = v.y;
            tc[4 * i + 2] = v.z; tc[4 * i + 3] = v.w;
        }

        // classification loss
        float cls = 0.0f;
        #pragma unroll
        for (int c = 0; c < 20; c++) {
            float d = p[10 + c] - tc[c];
            cls = fmaf(d, d, cls);
        }
        s_cls = fm * cls;

        // no-object confidence loss (raw; x0.5 in finalize)
        s_no = (1.0f - fm) * (p[4] * p[4] + p[9] * p[9]);

        // target box in xyxy
        const float invS = 1.0f / (float)SGRID;
        float tx = tb.x * invS, ty = tb.y * invS;
        float t0 = tx - 0.5f * tb.z, t1 = ty - 0.5f * tb.w;
        float t2 = tx + 0.5f * tb.z, t3 = ty + 0.5f * tb.w;

        float i1 = iou_vs_t(p,     t0, t1, t2, t3);
        float i2 = iou_vs_t(p + 5, t0, t1, t2, t3);
        bool take1 = i1 > i2;
        const float* bb = take1 ? p : (p + 5);
        float best_iou = take1 ? i1 : i2;

        // xy loss
        float dx = bb[0] - tb.x, dy = bb[1] - tb.y;
        float xy = dx * dx + dy * dy;

        // wh loss (reference substitutes 1.0 when mask false; term is fm-masked anyway)
        bool on = fm > 0.0f;
        float bw = on ? bb[2] : 1.0f, bh = on ? bb[3] : 1.0f;
        float tw = on ? tb.z  : 1.0f, th = on ? tb.w  : 1.0f;
        float dw = sqrtf(bw) - sqrtf(tw);
        float dh = sqrtf(bh) - sqrtf(th);
        float wh = dw * dw + dh * dh;

        s_reg = fm * (xy + wh);  // raw; x5 in finalize

        float dc = bb[4] - best_iou;
        s_ct = fm * dc * dc;
    }

    // --- reduction: warp shuffle -> shared -> block -> fp64 atomics ---
    #pragma unroll
    for (int off = 16; off > 0; off >>= 1) {
        s_cls += __shfl_down_sync(0xFFFFFFFFu, s_cls, off);
        s_no  += __shfl_down_sync(0xFFFFFFFFu, s_no,  off);
        s_reg += __shfl_down_sync(0xFFFFFFFFu, s_reg, off);
        s_ct  += __shfl_down_sync(0xFFFFFFFFu, s_ct,  off);
    }
    __shared__ float4 s_part[8];  // 256 threads / 32
    int wid = threadIdx.x >> 5, lid = threadIdx.x & 31;
    if (lid == 0) s_part[wid] = make_float4(s_cls, s_no, s_reg, s_ct);
    __syncthreads();
    if (wid == 0) {
        float4 v = (lid < 8) ? s_part[lid] : make_float4(0.f, 0.f, 0.f, 0.f);
        #pragma unroll
        for (int off = 4; off > 0; off >>= 1) {
            v.x += __shfl_down_sync(0xFFFFFFFFu, v.x, off);
            v.y += __shfl_down_sync(0xFFFFFFFFu, v.y, off);
            v.z += __shfl_down_sync(0xFFFFFFFFu, v.z, off);
            v.w += __shfl_down_sync(0xFFFFFFFFu, v.w, off);
        }
        if (lid == 0) {
            atomicAdd(&g_acc[0], (double)v.x);
            atomicAdd(&g_acc[1], (double)v.y);
            atomicAdd(&g_acc[2], (double)v.z);
            atomicAdd(&g_acc[3], (double)v.w);
        }
    }
}

__global__ void finalize_kernel(float* __restrict__ out, double invN) {
    double cls = g_acc[0];
    double no  = L_NOOBJ * g_acc[1];
    double reg = L_COORD * g_acc[2];
    double ct  = g_acc[3];
    double tot = cls + no + reg + ct;
    out[0] = (float)(tot * invN);
    out[1] = (float)(reg * invN);
    out[2] = (float)(ct  * invN);
    out[3] = (float)(no  * invN);
    out[4] = (float)(cls * invN);
}

extern "C" void kernel_launch(void* const* d_in, const int* in_sizes, int n_in,
                              void* d_out, int out_size) {
    const float* pred = (const float*)d_in[0];
    const float* tbox = (const float*)d_in[1];
    const float* tcls = (const float*)d_in[2];
    const void*  mask = d_in[3];

    int ncells = in_sizes[0] / 30;              // N * 28 * 28
    int nbatch = ncells / (SGRID * SGRID);      // N
    double invN = 1.0 / (double)nbatch;

    detect_and_zero_kernel<<<1, 256>>>((const unsigned char*)mask);
    int threads = 256;
    int blocks = (ncells + threads - 1) / threads;
    yolo_loss_kernel<<<blocks, threads>>>(pred, tbox, tcls, mask, ncells);
    finalize_kernel<<<1, 1>>>((float*)d_out, invN);
}